// round 7
// baseline (speedup 1.0000x reference)
#include <cuda_runtime.h>
#include <cstdint>
#include <cstddef>

// Problem constants
#define BATCH 4
#define SEQ   2048
#define EMB   512
#define HEADS 8
#define KDIM  64
#define TOKENS (BATCH * SEQ)          // 8192

// Scratch (allocation-free rule: __device__ globals)
__device__ float g_q  [TOKENS * EMB];   // Q = x @ Wq, [tok, h*64+d]
__device__ float g_ctx[TOKENS * EMB];   // context,    [tok, h*64+d]

// ---------------------------------------------------------------------------
// helpers
// ---------------------------------------------------------------------------
__device__ __forceinline__ uint32_t pack2(float lo, float hi) {
    uint32_t r;
    asm("cvt.rn.bf16x2.f32 %0, %1, %2;" : "=r"(r) : "f"(hi), "f"(lo));
    return r;
}
__device__ __forceinline__ float unlo(uint32_t p) { return __uint_as_float(p << 16); }
__device__ __forceinline__ float unhi(uint32_t p) { return __uint_as_float(p & 0xffff0000u); }
__device__ __forceinline__ uint32_t resid2(float lo, float hi, uint32_t h) {
    return pack2(lo - unlo(h), hi - unhi(h));
}
__device__ __forceinline__ void mma_bf16(float* c,
                                         uint32_t a0, uint32_t a1, uint32_t a2, uint32_t a3,
                                         uint32_t b0, uint32_t b1)
{
    asm volatile(
        "mma.sync.aligned.m16n8k16.row.col.f32.bf16.bf16.f32 "
        "{%0,%1,%2,%3}, {%4,%5,%6,%7}, {%8,%9}, {%0,%1,%2,%3};\n"
        : "+f"(c[0]), "+f"(c[1]), "+f"(c[2]), "+f"(c[3])
        : "r"(a0), "r"(a1), "r"(a2), "r"(a3), "r"(b0), "r"(b1));
}
__device__ __forceinline__ uint32_t smem_u32(const void* p) {
    uint32_t a;
    asm("{ .reg .u64 t; cvta.to.shared.u64 t, %1; cvt.u32.u64 %0, t; }" : "=r"(a) : "l"(p));
    return a;
}
__device__ __forceinline__ void cp16(uint32_t dst, const void* src) {
    asm volatile("cp.async.cg.shared.global [%0], [%1], 16;" :: "r"(dst), "l"(src));
}
#define CP_COMMIT() asm volatile("cp.async.commit_group;" ::: "memory")
#define CP_WAIT0()  asm volatile("cp.async.wait_group 0;" ::: "memory")

// packed smem row widths (uint32 words) — conflict-free fragment LDS
#define KW 36
#define VW 72
#define AW 20

// ===========================================================================
// Split-bf16 GEMM (round-4 version, known good): C = A @ B, 128x64, BK=32.
// ===========================================================================
__global__ __launch_bounds__(256) void gemm_bf16s(
    const float* __restrict__ A, const float* __restrict__ Bm,
    float* __restrict__ C, int M, int N, int K)
{
    __shared__ uint32_t Ahi[128 * AW], Alo[128 * AW];
    __shared__ uint32_t Bhi[16 * VW],  Blo[16 * VW];

    const int tid  = threadIdx.x;
    const int warp = tid >> 5, lane = tid & 31;
    const int g = lane >> 2, t = lane & 3;
    const int bn = blockIdx.x << 6;
    const int bm = blockIdx.y << 7;
    const int wm = warp << 4;

    float acc[8][4];
#pragma unroll
    for (int n = 0; n < 8; ++n)
#pragma unroll
        for (int i = 0; i < 4; ++i) acc[n][i] = 0.f;

    for (int kt = 0; kt < K; kt += 32) {
        __syncthreads();
        {
            const int r   = tid >> 1;
            const int c16 = (tid & 1) << 4;
            const float* ar = &A[(size_t)(bm + r) * K + kt + c16];
#pragma unroll
            for (int i = 0; i < 4; ++i) {
                float4 a = *(const float4*)&ar[4 * i];
                uint32_t h0 = pack2(a.x, a.y), h1 = pack2(a.z, a.w);
                int w = r * AW + (c16 >> 1) + 2 * i;
                *(uint2*)&Ahi[w] = make_uint2(h0, h1);
                *(uint2*)&Alo[w] = make_uint2(resid2(a.x, a.y, h0), resid2(a.z, a.w, h1));
            }
            const int nn = (tid & 31) << 1;
            const int kk = (tid >> 5) << 2;
#pragma unroll
            for (int i = 0; i < 2; ++i) {
                int r0 = kk + 2 * i;
                float2 p = *(const float2*)&Bm[(size_t)(kt + r0)     * N + bn + nn];
                float2 q = *(const float2*)&Bm[(size_t)(kt + r0 + 1) * N + bn + nn];
                uint32_t h0 = pack2(p.x, q.x), h1 = pack2(p.y, q.y);
                int w = (r0 >> 1) * VW + nn;
                *(uint2*)&Bhi[w] = make_uint2(h0, h1);
                *(uint2*)&Blo[w] = make_uint2(resid2(p.x, q.x, h0), resid2(p.y, q.y, h1));
            }
        }
        __syncthreads();

#pragma unroll
        for (int kc = 0; kc < 2; ++kc) {
            const int wa = (wm + g) * AW + kc * 8 + t;
            uint32_t ah0 = Ahi[wa],     ah1 = Ahi[wa + 8 * AW];
            uint32_t ah2 = Ahi[wa + 4], ah3 = Ahi[wa + 8 * AW + 4];
            uint32_t al0 = Alo[wa],     al1 = Alo[wa + 8 * AW];
            uint32_t al2 = Alo[wa + 4], al3 = Alo[wa + 8 * AW + 4];
#pragma unroll
            for (int n = 0; n < 8; ++n) {
                const int wb = (kc * 8 + t) * VW + n * 8 + g;
                uint32_t bh0 = Bhi[wb], bh1 = Bhi[wb + 4 * VW];
                uint32_t bl0 = Blo[wb], bl1 = Blo[wb + 4 * VW];
                mma_bf16(acc[n], ah0, ah1, ah2, ah3, bh0, bh1);
                mma_bf16(acc[n], al0, al1, al2, al3, bh0, bh1);
                mma_bf16(acc[n], ah0, ah1, ah2, ah3, bl0, bl1);
            }
        }
    }

    const int row0 = bm + wm + g, row1 = row0 + 8;
#pragma unroll
    for (int n = 0; n < 8; ++n) {
        *(float2*)&C[(size_t)row0 * N + bn + n * 8 + 2 * t] = make_float2(acc[n][0], acc[n][1]);
        *(float2*)&C[(size_t)row1 * N + bn + n * 8 + 2 * t] = make_float2(acc[n][2], acc[n][3]);
    }
}

// ===========================================================================
// Flash attention: round-4 compute core (online softmax, split-bf16 mma.sync)
// + cp.async K/V prefetch into DOUBLE-BUFFERED raw stage (hazard-free:
// cp writes buf (kt+1)&1 while convert reads buf kt&1 — disjoint regions).
// 1 CTA = 8 warps per (b, h, 128-query tile); warp owns 16 q rows.
// ===========================================================================
// smem (bytes):
//   raw K/V buf0: K @0 (17408 = 64 rows x 68 f32), V @17408
//   raw K/V buf1: K @34816,  V @52224
//   packed: Khi @69632 (9216) | Klo @78848 | Vhi @88064 (9216) | Vlo @97280
#define A_KRAW0 0
#define A_VRAW0 17408
#define A_KRAW1 34816
#define A_VRAW1 52224
#define A_KHI   69632
#define A_KLO   78848
#define A_VHI   88064
#define A_VLO   97280
#define ATTN_SMEM 106496

__global__ __launch_bounds__(256) void attn_mma(
    const float* __restrict__ Q,   // [tok, 512] from g_q
    const float* __restrict__ Kg,  // [B,H,S,64]
    const float* __restrict__ Vg,  // [B,H,S,64]
    float* __restrict__ Ctx)       // [tok, 512]
{
    extern __shared__ char smem[];
    uint32_t* Khi = (uint32_t*)(smem + A_KHI);
    uint32_t* Klo = (uint32_t*)(smem + A_KLO);
    uint32_t* Vhi = (uint32_t*)(smem + A_VHI);
    uint32_t* Vlo = (uint32_t*)(smem + A_VLO);
    const uint32_t sb = smem_u32(smem);

    const int tid  = threadIdx.x;
    const int warp = tid >> 5, lane = tid & 31;
    const int gq = lane >> 2, tq = lane & 3;
    const int bh = blockIdx.y;
    const int b  = bh >> 3, h = bh & 7;
    const int q0 = blockIdx.x << 7;
    const int row0 = q0 + warp * 16 + gq;
    const int row1 = row0 + 8;

    const float* kb = Kg + (size_t)bh * SEQ * KDIM;
    const float* vb = Vg + (size_t)bh * SEQ * KDIM;

    // cp.async mapping: row = tid>>2, 16-float chunk base (tid&3)*16
    const int crw = tid >> 2, cch = (tid & 3) << 4;
    // convert mappings (round-4 packed layouts)
    const int lr  = tid >> 2, lc = (tid & 3) << 4;            // K convert
    const int ld2 = (tid & 31) << 1, lrr = (tid >> 5) << 3;   // V convert

    // ---- Q fragments (bf16 hi/lo), pre-scaled by 1/sqrt(64) ----
    uint32_t qh[4][4], ql[4][4];
    {
        const float* qp = Q + (size_t)(b * SEQ) * EMB + h * KDIM;
#pragma unroll
        for (int kc = 0; kc < 4; ++kc) {
            float2 v0 = *(const float2*)&qp[(size_t)row0 * EMB + kc * 16 + 2 * tq];
            float2 v1 = *(const float2*)&qp[(size_t)row1 * EMB + kc * 16 + 2 * tq];
            float2 v2 = *(const float2*)&qp[(size_t)row0 * EMB + kc * 16 + 2 * tq + 8];
            float2 v3 = *(const float2*)&qp[(size_t)row1 * EMB + kc * 16 + 2 * tq + 8];
            v0.x *= 0.125f; v0.y *= 0.125f; v1.x *= 0.125f; v1.y *= 0.125f;
            v2.x *= 0.125f; v2.y *= 0.125f; v3.x *= 0.125f; v3.y *= 0.125f;
            qh[kc][0] = pack2(v0.x, v0.y); ql[kc][0] = resid2(v0.x, v0.y, qh[kc][0]);
            qh[kc][1] = pack2(v1.x, v1.y); ql[kc][1] = resid2(v1.x, v1.y, qh[kc][1]);
            qh[kc][2] = pack2(v2.x, v2.y); ql[kc][2] = resid2(v2.x, v2.y, qh[kc][2]);
            qh[kc][3] = pack2(v3.x, v3.y); ql[kc][3] = resid2(v3.x, v3.y, qh[kc][3]);
        }
    }

    float oacc[8][4];
#pragma unroll
    for (int n = 0; n < 8; ++n)
#pragma unroll
        for (int i = 0; i < 4; ++i) oacc[n][i] = 0.f;
    float m0 = -1e30f, m1 = -1e30f, l0 = 0.f, l1 = 0.f;

    // ---- prologue: stream tile 0 into raw buf 0 ----
    {
        const float* kp = &kb[(size_t)crw * KDIM + cch];
        const float* vp = &vb[(size_t)crw * KDIM + cch];
        uint32_t kd = sb + A_KRAW0 + crw * 272 + cch * 4;
        uint32_t vd = sb + A_VRAW0 + crw * 272 + cch * 4;
#pragma unroll
        for (int i = 0; i < 4; ++i) { cp16(kd + 16 * i, kp + 4 * i); cp16(vd + 16 * i, vp + 4 * i); }
        CP_COMMIT();
    }

    for (int kt = 0; kt < SEQ / 64; ++kt) {
        // raw[kt&1] complete for all threads; packed free (prev compute done)
        CP_WAIT0();
        __syncthreads();

        // ---- issue cp for tile kt+1 into the OTHER raw buffer ----
        if (kt < SEQ / 64 - 1) {
            const uint32_t kbase = ((kt + 1) & 1) ? A_KRAW1 : A_KRAW0;
            const uint32_t vbase = ((kt + 1) & 1) ? A_VRAW1 : A_VRAW0;
            const float* kp = &kb[((size_t)((kt + 1) << 6) + crw) * KDIM + cch];
            const float* vp = &vb[((size_t)((kt + 1) << 6) + crw) * KDIM + cch];
            uint32_t kd = sb + kbase + crw * 272 + cch * 4;
            uint32_t vd = sb + vbase + crw * 272 + cch * 4;
#pragma unroll
            for (int i = 0; i < 4; ++i) { cp16(kd + 16 * i, kp + 4 * i); cp16(vd + 16 * i, vp + 4 * i); }
            CP_COMMIT();
        }

        // ---- convert raw[kt&1] -> packed ----
        {
            const float* kraw = (const float*)(smem + ((kt & 1) ? A_KRAW1 : A_KRAW0));
            const float* vraw = (const float*)(smem + ((kt & 1) ? A_VRAW1 : A_VRAW0));
            const float* kp = &kraw[lr * 68 + lc];
#pragma unroll
            for (int i = 0; i < 4; ++i) {
                float4 kv = *(const float4*)&kp[4 * i];
                uint32_t h0 = pack2(kv.x, kv.y), h1 = pack2(kv.z, kv.w);
                int w = lr * KW + (lc >> 1) + 2 * i;
                *(uint2*)&Khi[w] = make_uint2(h0, h1);
                *(uint2*)&Klo[w] = make_uint2(resid2(kv.x, kv.y, h0), resid2(kv.z, kv.w, h1));
            }
#pragma unroll
            for (int i = 0; i < 4; ++i) {
                int r0 = lrr + 2 * i;
                float2 a = *(const float2*)&vraw[r0 * 68 + ld2];
                float2 c = *(const float2*)&vraw[(r0 + 1) * 68 + ld2];
                uint32_t h0 = pack2(a.x, c.x), h1 = pack2(a.y, c.y);
                int w = (r0 >> 1) * VW + ld2;
                *(uint2*)&Vhi[w] = make_uint2(h0, h1);
                *(uint2*)&Vlo[w] = make_uint2(resid2(a.x, c.x, h0), resid2(a.y, c.y, h1));
            }
        }
        __syncthreads();

        // ---- S = Q K^T (16x64 per warp) ----
        float sacc[8][4];
#pragma unroll
        for (int n = 0; n < 8; ++n)
#pragma unroll
            for (int i = 0; i < 4; ++i) sacc[n][i] = 0.f;

#pragma unroll
        for (int kc = 0; kc < 4; ++kc) {
#pragma unroll
            for (int n = 0; n < 8; ++n) {
                const int wb = (n * 8 + gq) * KW + kc * 8 + tq;
                uint32_t bh0 = Khi[wb], bh1 = Khi[wb + 4];
                uint32_t bl0 = Klo[wb], bl1 = Klo[wb + 4];
                mma_bf16(sacc[n], qh[kc][0], qh[kc][1], qh[kc][2], qh[kc][3], bh0, bh1);
                mma_bf16(sacc[n], ql[kc][0], ql[kc][1], ql[kc][2], ql[kc][3], bh0, bh1);
                mma_bf16(sacc[n], qh[kc][0], qh[kc][1], qh[kc][2], qh[kc][3], bl0, bl1);
            }
        }

        // ---- online softmax (quad-reduce; row0 via c0/c1, row1 via c2/c3) ----
        float tm0 = -1e30f, tm1 = -1e30f;
#pragma unroll
        for (int n = 0; n < 8; ++n) {
            tm0 = fmaxf(tm0, fmaxf(sacc[n][0], sacc[n][1]));
            tm1 = fmaxf(tm1, fmaxf(sacc[n][2], sacc[n][3]));
        }
        tm0 = fmaxf(tm0, __shfl_xor_sync(0xffffffffu, tm0, 1));
        tm0 = fmaxf(tm0, __shfl_xor_sync(0xffffffffu, tm0, 2));
        tm1 = fmaxf(tm1, __shfl_xor_sync(0xffffffffu, tm1, 1));
        tm1 = fmaxf(tm1, __shfl_xor_sync(0xffffffffu, tm1, 2));
        float n0 = fmaxf(m0, tm0), n1 = fmaxf(m1, tm1);
        float sc0 = __expf(m0 - n0), sc1 = __expf(m1 - n1);
        m0 = n0; m1 = n1;
        float ps0 = 0.f, ps1 = 0.f;
#pragma unroll
        for (int n = 0; n < 8; ++n) {
            sacc[n][0] = __expf(sacc[n][0] - n0); ps0 += sacc[n][0];
            sacc[n][1] = __expf(sacc[n][1] - n0); ps0 += sacc[n][1];
            sacc[n][2] = __expf(sacc[n][2] - n1); ps1 += sacc[n][2];
            sacc[n][3] = __expf(sacc[n][3] - n1); ps1 += sacc[n][3];
        }
        ps0 += __shfl_xor_sync(0xffffffffu, ps0, 1);
        ps0 += __shfl_xor_sync(0xffffffffu, ps0, 2);
        ps1 += __shfl_xor_sync(0xffffffffu, ps1, 1);
        ps1 += __shfl_xor_sync(0xffffffffu, ps1, 2);
        l0 = l0 * sc0 + ps0;
        l1 = l1 * sc1 + ps1;
#pragma unroll
        for (int n = 0; n < 8; ++n) {
            oacc[n][0] *= sc0; oacc[n][1] *= sc0;
            oacc[n][2] *= sc1; oacc[n][3] *= sc1;
        }

        // ---- O += P V : accumulator pairs pack directly into A fragments ----
#pragma unroll
        for (int j = 0; j < 4; ++j) {
            uint32_t ph0 = pack2(sacc[2*j][0],   sacc[2*j][1]);
            uint32_t ph1 = pack2(sacc[2*j][2],   sacc[2*j][3]);
            uint32_t ph2 = pack2(sacc[2*j+1][0], sacc[2*j+1][1]);
            uint32_t ph3 = pack2(sacc[2*j+1][2], sacc[2*j+1][3]);
            uint32_t pl0 = resid2(sacc[2*j][0],   sacc[2*j][1],   ph0);
            uint32_t pl1 = resid2(sacc[2*j][2],   sacc[2*j][3],   ph1);
            uint32_t pl2 = resid2(sacc[2*j+1][0], sacc[2*j+1][1], ph2);
            uint32_t pl3 = resid2(sacc[2*j+1][2], sacc[2*j+1][3], ph3);
#pragma unroll
            for (int dt = 0; dt < 8; ++dt) {
                const int wb = (j * 8 + tq) * VW + dt * 8 + gq;
                uint32_t bh0 = Vhi[wb], bh1 = Vhi[wb + 4 * VW];
                uint32_t bl0 = Vlo[wb], bl1 = Vlo[wb + 4 * VW];
                mma_bf16(oacc[dt], ph0, ph1, ph2, ph3, bh0, bh1);
                mma_bf16(oacc[dt], pl0, pl1, pl2, pl3, bh0, bh1);
                mma_bf16(oacc[dt], ph0, ph1, ph2, ph3, bl0, bl1);
            }
        }
    }

    // ---- normalize + write ctx [tok, h*64+d] ----
    float inv0 = 1.f / l0, inv1 = 1.f / l1;
    float* cp = Ctx + (size_t)(b * SEQ) * EMB + h * KDIM;
#pragma unroll
    for (int dt = 0; dt < 8; ++dt) {
        *(float2*)&cp[(size_t)row0 * EMB + dt * 8 + 2 * tq] =
            make_float2(oacc[dt][0] * inv0, oacc[dt][1] * inv0);
        *(float2*)&cp[(size_t)row1 * EMB + dt * 8 + 2 * tq] =
            make_float2(oacc[dt][2] * inv1, oacc[dt][3] * inv1);
    }
}

// ---------------------------------------------------------------------------
extern "C" void kernel_launch(void* const* d_in, const int* in_sizes, int n_in,
                              void* d_out, int out_size)
{
    const float* x   = (const float*)d_in[0];   // [4,2048,512]
    const float* key = (const float*)d_in[1];   // [4,8,2048,64]
    const float* val = (const float*)d_in[2];   // [4,8,2048,64]
    const float* wq  = (const float*)d_in[3];   // [512,512]
    const float* wo  = (const float*)d_in[4];   // [512,512]
    float* out = (float*)d_out;                 // [4,2048,512]

    float *qptr, *cptr;
    cudaGetSymbolAddress((void**)&qptr, g_q);
    cudaGetSymbolAddress((void**)&cptr, g_ctx);

    cudaFuncSetAttribute(attn_mma, cudaFuncAttributeMaxDynamicSharedMemorySize, ATTN_SMEM);

    // 1) Q = x @ Wq
    gemm_bf16s<<<dim3(EMB / 64, TOKENS / 128), 256>>>(x, wq, qptr, TOKENS, EMB, EMB);
    // 2) attention: grid (q-tiles of 128, b*h)
    attn_mma<<<dim3(SEQ / 128, BATCH * HEADS), 256, ATTN_SMEM>>>(qptr, key, val, cptr);
    // 3) out = ctx @ Wo
    gemm_bf16s<<<dim3(EMB / 64, TOKENS / 128), 256>>>(cptr, wo, out, TOKENS, EMB, EMB);
}

// round 9
// speedup vs baseline: 1.0326x; 1.0326x over previous
#include <cuda_runtime.h>
#include <cstdint>
#include <cstddef>

// Problem constants
#define BATCH 4
#define SEQ   2048
#define EMB   512
#define HEADS 8
#define KDIM  64
#define TOKENS (BATCH * SEQ)          // 8192

// Scratch (allocation-free rule: __device__ globals)
__device__ float g_q  [TOKENS * EMB];   // Q = x @ Wq, [tok, h*64+d]
__device__ float g_ctx[TOKENS * EMB];   // context,    [tok, h*64+d]

// ---------------------------------------------------------------------------
// helpers
// ---------------------------------------------------------------------------
__device__ __forceinline__ uint32_t pack2(float lo, float hi) {
    uint32_t r;
    asm("cvt.rn.bf16x2.f32 %0, %1, %2;" : "=r"(r) : "f"(hi), "f"(lo));
    return r;
}
__device__ __forceinline__ float unlo(uint32_t p) { return __uint_as_float(p << 16); }
__device__ __forceinline__ float unhi(uint32_t p) { return __uint_as_float(p & 0xffff0000u); }
__device__ __forceinline__ uint32_t resid2(float lo, float hi, uint32_t h) {
    return pack2(lo - unlo(h), hi - unhi(h));
}
__device__ __forceinline__ void mma_bf16(float* c,
                                         uint32_t a0, uint32_t a1, uint32_t a2, uint32_t a3,
                                         uint32_t b0, uint32_t b1)
{
    asm volatile(
        "mma.sync.aligned.m16n8k16.row.col.f32.bf16.bf16.f32 "
        "{%0,%1,%2,%3}, {%4,%5,%6,%7}, {%8,%9}, {%0,%1,%2,%3};\n"
        : "+f"(c[0]), "+f"(c[1]), "+f"(c[2]), "+f"(c[3])
        : "r"(a0), "r"(a1), "r"(a2), "r"(a3), "r"(b0), "r"(b1));
}

#define AW 20   // A-style packed row width (uint32 words)

// ===========================================================================
// Split-bf16 GEMM: C = A @ B, 128x64 tile, BK=32, interleaved B operands.
// Bint[kc*1024 + c*16 + ((t+c)&3)*4] = {b0h, b1h, b0l, b1l},
//   b0 = rows (16kc+2t, +1), b1 = rows (16kc+2t+8, +9), col c.
// ===========================================================================
__global__ __launch_bounds__(256) void gemm_bf16s(
    const float* __restrict__ A, const float* __restrict__ Bm,
    float* __restrict__ C, int M, int N, int K)
{
    __shared__ __align__(16) uint32_t Ahi[128 * AW], Alo[128 * AW];
    __shared__ __align__(16) uint32_t Bint[2048];

    const int tid  = threadIdx.x;
    const int warp = tid >> 5, lane = tid & 31;
    const int g = lane >> 2, t = lane & 3;
    const int bn = blockIdx.x << 6;
    const int bm = blockIdx.y << 7;
    const int wm = warp << 4;

    // B converter mapping
    const int bkc = tid >> 7, bts = (tid >> 5) & 3, bc0 = tid & 31;

    float acc[8][4];
#pragma unroll
    for (int n = 0; n < 8; ++n)
#pragma unroll
        for (int i = 0; i < 4; ++i) acc[n][i] = 0.f;

    for (int kt = 0; kt < K; kt += 32) {
        __syncthreads();
        {   // A tile 128x32: thread = half row (16 cols)
            const int r   = tid >> 1;
            const int c16 = (tid & 1) << 4;
            const float* ar = &A[(size_t)(bm + r) * K + kt + c16];
#pragma unroll
            for (int i = 0; i < 4; ++i) {
                float4 a = *(const float4*)&ar[4 * i];
                uint32_t h0 = pack2(a.x, a.y), h1 = pack2(a.z, a.w);
                int w = r * AW + (c16 >> 1) + 2 * i;
                *(uint2*)&Ahi[w] = make_uint2(h0, h1);
                *(uint2*)&Alo[w] = make_uint2(resid2(a.x, a.y, h0), resid2(a.z, a.w, h1));
            }
            // B tile 32x64 -> interleaved
            const int rb = kt + 16 * bkc + 2 * bts;
#pragma unroll
            for (int i = 0; i < 2; ++i) {
                const int c = bc0 + 32 * i;
                float v0 = Bm[(size_t)rb       * N + bn + c];
                float v1 = Bm[(size_t)(rb + 1) * N + bn + c];
                float v2 = Bm[(size_t)(rb + 8) * N + bn + c];
                float v3 = Bm[(size_t)(rb + 9) * N + bn + c];
                uint32_t b0h = pack2(v0, v1), b1h = pack2(v2, v3);
                uint32_t b0l = resid2(v0, v1, b0h), b1l = resid2(v2, v3, b1h);
                *(uint4*)&Bint[bkc * 1024 + c * 16 + (((bts + c) & 3) << 2)] =
                    make_uint4(b0h, b1h, b0l, b1l);
            }
        }
        __syncthreads();

#pragma unroll
        for (int kc = 0; kc < 2; ++kc) {
            const int wa = (wm + g) * AW + kc * 8 + t;
            uint32_t ah0 = Ahi[wa],     ah1 = Ahi[wa + 8 * AW];
            uint32_t ah2 = Ahi[wa + 4], ah3 = Ahi[wa + 8 * AW + 4];
            uint32_t al0 = Alo[wa],     al1 = Alo[wa + 8 * AW];
            uint32_t al2 = Alo[wa + 4], al3 = Alo[wa + 8 * AW + 4];
#pragma unroll
            for (int n = 0; n < 8; ++n) {
                uint4 bb = *(const uint4*)&Bint[kc * 1024 + (n * 8 + g) * 16 + (((t + g) & 3) << 2)];
                mma_bf16(acc[n], ah0, ah1, ah2, ah3, bb.x, bb.y);
                mma_bf16(acc[n], al0, al1, al2, al3, bb.x, bb.y);
                mma_bf16(acc[n], ah0, ah1, ah2, ah3, bb.z, bb.w);
            }
        }
    }

    const int row0 = bm + wm + g, row1 = row0 + 8;
#pragma unroll
    for (int n = 0; n < 8; ++n) {
        *(float2*)&C[(size_t)row0 * N + bn + n * 8 + 2 * t] = make_float2(acc[n][0], acc[n][1]);
        *(float2*)&C[(size_t)row1 * N + bn + n * 8 + 2 * t] = make_float2(acc[n][2], acc[n][3]);
    }
}

// ===========================================================================
// Flash attention: split-bf16 mma.sync, interleaved B operands, ONLINE
// softmax (round-4 numerics — logits can exceed +150 due to the correlated
// all-ones component of Wq, so a fixed max overflows; online rescale is
// mandatory).
// 1 CTA = 8 warps per (b, h, 128-query tile); warp owns 16 q rows.
// Kint[key*80 + kc*16 + ((t+kc)&3)*4]  = {b0h,b1h,b0l,b1l} (dpairs of key)
// Vint[j*1024 + d*16 + ((t+d)&3)*4]    = {b0h,b1h,b0l,b1l} (keypairs, dim d)
// ===========================================================================
__global__ __launch_bounds__(256) void attn_mma(
    const float* __restrict__ Q,   // [tok, 512] from g_q
    const float* __restrict__ Kg,  // [B,H,S,64]
    const float* __restrict__ Vg,  // [B,H,S,64]
    float* __restrict__ Ctx)       // [tok, 512]
{
    __shared__ __align__(16) uint32_t Kint[64 * 80];   // 20480 B
    __shared__ __align__(16) uint32_t Vint[4096];      // 16384 B

    const int tid  = threadIdx.x;
    const int warp = tid >> 5, lane = tid & 31;
    const int gq = lane >> 2, tq = lane & 3;
    const int bh = blockIdx.y;
    const int b  = bh >> 3, h = bh & 7;
    const int q0 = blockIdx.x << 7;
    const int row0 = q0 + warp * 16 + gq;
    const int row1 = row0 + 8;

    const float* kb = Kg + (size_t)bh * SEQ * KDIM;
    const float* vb = Vg + (size_t)bh * SEQ * KDIM;

    // K converter mapping: key row + 16-dim chunk
    const int lr = tid >> 2, kcb = tid & 3;
    // V converter mapping: j group, t slot, dim base
    const int vj = tid >> 6, vts = (tid >> 4) & 3, vd0 = tid & 15;

    // ---- Q fragments (bf16 hi/lo), pre-scaled by 1/sqrt(64) ----
    uint32_t qh[4][4], ql[4][4];
    {
        const float* qp = Q + (size_t)(b * SEQ) * EMB + h * KDIM;
#pragma unroll
        for (int kc = 0; kc < 4; ++kc) {
            float2 v0 = *(const float2*)&qp[(size_t)row0 * EMB + kc * 16 + 2 * tq];
            float2 v1 = *(const float2*)&qp[(size_t)row1 * EMB + kc * 16 + 2 * tq];
            float2 v2 = *(const float2*)&qp[(size_t)row0 * EMB + kc * 16 + 2 * tq + 8];
            float2 v3 = *(const float2*)&qp[(size_t)row1 * EMB + kc * 16 + 2 * tq + 8];
            v0.x *= 0.125f; v0.y *= 0.125f; v1.x *= 0.125f; v1.y *= 0.125f;
            v2.x *= 0.125f; v2.y *= 0.125f; v3.x *= 0.125f; v3.y *= 0.125f;
            qh[kc][0] = pack2(v0.x, v0.y); ql[kc][0] = resid2(v0.x, v0.y, qh[kc][0]);
            qh[kc][1] = pack2(v1.x, v1.y); ql[kc][1] = resid2(v1.x, v1.y, qh[kc][1]);
            qh[kc][2] = pack2(v2.x, v2.y); ql[kc][2] = resid2(v2.x, v2.y, qh[kc][2]);
            qh[kc][3] = pack2(v3.x, v3.y); ql[kc][3] = resid2(v3.x, v3.y, qh[kc][3]);
        }
    }

    float oacc[8][4];
#pragma unroll
    for (int n = 0; n < 8; ++n)
#pragma unroll
        for (int i = 0; i < 4; ++i) oacc[n][i] = 0.f;
    float m0 = -1e30f, m1 = -1e30f, l0 = 0.f, l1 = 0.f;

    for (int kt = 0; kt < SEQ / 64; ++kt) {
        __syncthreads();
        {   // ---- K tile convert: thread = (key lr, dims 16*kcb..+15) ----
            const float* kr = &kb[((size_t)(kt << 6) + lr) * KDIM + kcb * 16];
            float4 a0 = *(const float4*)&kr[0],  a1 = *(const float4*)&kr[4];
            float4 a2 = *(const float4*)&kr[8],  a3 = *(const float4*)&kr[12];
            uint32_t hh[8], ll[8];
            hh[0] = pack2(a0.x, a0.y); ll[0] = resid2(a0.x, a0.y, hh[0]);
            hh[1] = pack2(a0.z, a0.w); ll[1] = resid2(a0.z, a0.w, hh[1]);
            hh[2] = pack2(a1.x, a1.y); ll[2] = resid2(a1.x, a1.y, hh[2]);
            hh[3] = pack2(a1.z, a1.w); ll[3] = resid2(a1.z, a1.w, hh[3]);
            hh[4] = pack2(a2.x, a2.y); ll[4] = resid2(a2.x, a2.y, hh[4]);
            hh[5] = pack2(a2.z, a2.w); ll[5] = resid2(a2.z, a2.w, hh[5]);
            hh[6] = pack2(a3.x, a3.y); ll[6] = resid2(a3.x, a3.y, hh[6]);
            hh[7] = pack2(a3.z, a3.w); ll[7] = resid2(a3.z, a3.w, hh[7]);
#pragma unroll
            for (int tt = 0; tt < 4; ++tt)
                *(uint4*)&Kint[lr * 80 + kcb * 16 + (((tt + kcb) & 3) << 2)] =
                    make_uint4(hh[tt], hh[tt + 4], ll[tt], ll[tt + 4]);

            // ---- V tile convert: thread = (j, t-slot, dims vd0+16m) ----
            const int k0 = 16 * vj + 2 * vts;
            const float* r0 = &vb[((size_t)(kt << 6) + k0) * KDIM];
            const float* r1 = r0 + KDIM;
            const float* r2 = r0 + 8 * KDIM;
            const float* r3 = r0 + 9 * KDIM;
#pragma unroll
            for (int m = 0; m < 4; ++m) {
                const int d = vd0 + 16 * m;
                float v0 = r0[d], v1 = r1[d], v2 = r2[d], v3 = r3[d];
                uint32_t b0h = pack2(v0, v1), b1h = pack2(v2, v3);
                uint32_t b0l = resid2(v0, v1, b0h), b1l = resid2(v2, v3, b1h);
                *(uint4*)&Vint[vj * 1024 + d * 16 + (((vts + vd0) & 3) << 2)] =
                    make_uint4(b0h, b1h, b0l, b1l);
            }
        }
        __syncthreads();

        // ---- S = Q K^T (16x64 per warp) ----
        float sacc[8][4];
#pragma unroll
        for (int n = 0; n < 8; ++n)
#pragma unroll
            for (int i = 0; i < 4; ++i) sacc[n][i] = 0.f;

#pragma unroll
        for (int kc = 0; kc < 4; ++kc) {
#pragma unroll
            for (int n = 0; n < 8; ++n) {
                uint4 bb = *(const uint4*)&Kint[(n * 8 + gq) * 80 + kc * 16 + (((tq + kc) & 3) << 2)];
                mma_bf16(sacc[n], qh[kc][0], qh[kc][1], qh[kc][2], qh[kc][3], bb.x, bb.y);
                mma_bf16(sacc[n], ql[kc][0], ql[kc][1], ql[kc][2], ql[kc][3], bb.x, bb.y);
                mma_bf16(sacc[n], qh[kc][0], qh[kc][1], qh[kc][2], qh[kc][3], bb.z, bb.w);
            }
        }

        // ---- online softmax (quad-reduce; row0 via c0/c1, row1 via c2/c3) ----
        float tm0 = -1e30f, tm1 = -1e30f;
#pragma unroll
        for (int n = 0; n < 8; ++n) {
            tm0 = fmaxf(tm0, fmaxf(sacc[n][0], sacc[n][1]));
            tm1 = fmaxf(tm1, fmaxf(sacc[n][2], sacc[n][3]));
        }
        tm0 = fmaxf(tm0, __shfl_xor_sync(0xffffffffu, tm0, 1));
        tm0 = fmaxf(tm0, __shfl_xor_sync(0xffffffffu, tm0, 2));
        tm1 = fmaxf(tm1, __shfl_xor_sync(0xffffffffu, tm1, 1));
        tm1 = fmaxf(tm1, __shfl_xor_sync(0xffffffffu, tm1, 2));
        float n0 = fmaxf(m0, tm0), n1 = fmaxf(m1, tm1);
        float sc0 = __expf(m0 - n0), sc1 = __expf(m1 - n1);
        m0 = n0; m1 = n1;
        float ps0 = 0.f, ps1 = 0.f;
#pragma unroll
        for (int n = 0; n < 8; ++n) {
            sacc[n][0] = __expf(sacc[n][0] - n0); ps0 += sacc[n][0];
            sacc[n][1] = __expf(sacc[n][1] - n0); ps0 += sacc[n][1];
            sacc[n][2] = __expf(sacc[n][2] - n1); ps1 += sacc[n][2];
            sacc[n][3] = __expf(sacc[n][3] - n1); ps1 += sacc[n][3];
        }
        ps0 += __shfl_xor_sync(0xffffffffu, ps0, 1);
        ps0 += __shfl_xor_sync(0xffffffffu, ps0, 2);
        ps1 += __shfl_xor_sync(0xffffffffu, ps1, 1);
        ps1 += __shfl_xor_sync(0xffffffffu, ps1, 2);
        l0 = l0 * sc0 + ps0;
        l1 = l1 * sc1 + ps1;
#pragma unroll
        for (int n = 0; n < 8; ++n) {
            oacc[n][0] *= sc0; oacc[n][1] *= sc0;
            oacc[n][2] *= sc1; oacc[n][3] *= sc1;
        }

        // ---- O += P V : accumulator pairs pack directly into A fragments ----
#pragma unroll
        for (int j = 0; j < 4; ++j) {
            uint32_t ph0 = pack2(sacc[2*j][0],   sacc[2*j][1]);
            uint32_t ph1 = pack2(sacc[2*j][2],   sacc[2*j][3]);
            uint32_t ph2 = pack2(sacc[2*j+1][0], sacc[2*j+1][1]);
            uint32_t ph3 = pack2(sacc[2*j+1][2], sacc[2*j+1][3]);
            uint32_t pl0 = resid2(sacc[2*j][0],   sacc[2*j][1],   ph0);
            uint32_t pl1 = resid2(sacc[2*j][2],   sacc[2*j][3],   ph1);
            uint32_t pl2 = resid2(sacc[2*j+1][0], sacc[2*j+1][1], ph2);
            uint32_t pl3 = resid2(sacc[2*j+1][2], sacc[2*j+1][3], ph3);
#pragma unroll
            for (int dt = 0; dt < 8; ++dt) {
                uint4 bb = *(const uint4*)&Vint[j * 1024 + (dt * 8 + gq) * 16 + (((tq + gq) & 3) << 2)];
                mma_bf16(oacc[dt], ph0, ph1, ph2, ph3, bb.x, bb.y);
                mma_bf16(oacc[dt], pl0, pl1, pl2, pl3, bb.x, bb.y);
                mma_bf16(oacc[dt], ph0, ph1, ph2, ph3, bb.z, bb.w);
            }
        }
    }

    // ---- normalize + write ctx [tok, h*64+d] ----
    float inv0 = 1.f / l0, inv1 = 1.f / l1;
    float* cp = Ctx + (size_t)(b * SEQ) * EMB + h * KDIM;
#pragma unroll
    for (int dt = 0; dt < 8; ++dt) {
        *(float2*)&cp[(size_t)row0 * EMB + dt * 8 + 2 * tq] =
            make_float2(oacc[dt][0] * inv0, oacc[dt][1] * inv0);
        *(float2*)&cp[(size_t)row1 * EMB + dt * 8 + 2 * tq] =
            make_float2(oacc[dt][2] * inv1, oacc[dt][3] * inv1);
    }
}

// ---------------------------------------------------------------------------
extern "C" void kernel_launch(void* const* d_in, const int* in_sizes, int n_in,
                              void* d_out, int out_size)
{
    const float* x   = (const float*)d_in[0];   // [4,2048,512]
    const float* key = (const float*)d_in[1];   // [4,8,2048,64]
    const float* val = (const float*)d_in[2];   // [4,8,2048,64]
    const float* wq  = (const float*)d_in[3];   // [512,512]
    const float* wo  = (const float*)d_in[4];   // [512,512]
    float* out = (float*)d_out;                 // [4,2048,512]

    float *qptr, *cptr;
    cudaGetSymbolAddress((void**)&qptr, g_q);
    cudaGetSymbolAddress((void**)&cptr, g_ctx);

    // 1) Q = x @ Wq
    gemm_bf16s<<<dim3(EMB / 64, TOKENS / 128), 256>>>(x, wq, qptr, TOKENS, EMB, EMB);
    // 2) attention: grid (q-tiles of 128, b*h)
    attn_mma<<<dim3(SEQ / 128, BATCH * HEADS), 256>>>(qptr, key, val, cptr);
    // 3) out = ctx @ Wo
    gemm_bf16s<<<dim3(EMB / 64, TOKENS / 128), 256>>>(cptr, wo, out, TOKENS, EMB, EMB);
}